// round 6
// baseline (speedup 1.0000x reference)
#include <cuda_runtime.h>
#include <cstdint>

#define N_ROWS 1024
#define X1D 256
#define X2D 128
#define HID 256
#define R 8                 // rows per block
#define NTHR 1024
#define NG 16               // k-groups (group h owns k === h mod 16)
#define CT 64               // col-threads per group (4 cols each)
#define KC 32               // k-rows per staged chunk (32KB)
#define NCHUNK (HID / KC)   // 8 chunks per layer
#define NBLK (N_ROWS / R)   // 128
#define SBLK 8              // stats blocks

typedef unsigned long long u64;

__device__ __forceinline__ u64 bcast2(float w) {
    u64 d; asm("mov.b64 %0, {%1, %1};" : "=l"(d) : "f"(w)); return d;
}
__device__ __forceinline__ u64 ffma2(u64 a, u64 b, u64 c) {
    u64 d; asm("fma.rn.f32x2 %0, %1, %2, %3;" : "=l"(d) : "l"(a), "l"(b), "l"(c));
    return d;
}
__device__ __forceinline__ u64 fadd2(u64 a, u64 b) {
    u64 d; asm("add.rn.f32x2 %0, %1, %2;" : "=l"(d) : "l"(a), "l"(b));
    return d;
}
__device__ __forceinline__ void unpack2(float& lo, float& hi, u64 v) {
    asm("mov.b64 {%0, %1}, %2;" : "=f"(lo), "=f"(hi) : "l"(v));
}
__device__ __forceinline__ void cp16(uint32_t s, const float* g) {
    asm volatile("cp.async.cg.shared.global [%0], [%1], 16;" :: "r"(s), "l"(g));
}
__device__ __forceinline__ void cp_commit() {
    asm volatile("cp.async.commit_group;");
}
__device__ __forceinline__ void cp_wait0() {
    asm volatile("cp.async.wait_group 0;");
}

// per-block partial column sums of x2 and x2^2
__device__ float g_part_m[SBLK * X2D];
__device__ float g_part_s[SBLK * X2D];

// ---------------------------------------------------------------------------
// Kernel 1: partial x2 column stats + zero out[0]
// ---------------------------------------------------------------------------
__global__ void __launch_bounds__(1024) club_stats_kernel(
    const float* __restrict__ x2, float* __restrict__ out)
{
    __shared__ float sm[8][128];
    __shared__ float sq[8][128];
    int t = threadIdx.x;
    int c = t & 127;
    int s = t >> 7;
    int r0 = blockIdx.x * 128 + s * 16;
    float a = 0.f, b = 0.f;
    #pragma unroll
    for (int i = 0; i < 16; i++) {
        float v = x2[(r0 + i) * X2D + c];
        a += v;
        b += v * v;
    }
    sm[s][c] = a;
    sq[s][c] = b;
    __syncthreads();
    if (t < 128) {
        float ma = 0.f, mb = 0.f;
        #pragma unroll
        for (int k = 0; k < 8; k++) { ma += sm[k][t]; mb += sq[k][t]; }
        g_part_m[blockIdx.x * X2D + t] = ma;
        g_part_s[blockIdx.x * X2D + t] = mb;
    }
    if (blockIdx.x == 0 && t == 0) out[0] = 0.0f;
}

// ---------------------------------------------------------------------------
// Kernel 2: fused 3-layer MLP + CLUB epilogue.
// f32x2 packed math; weights staged via cp.async into double-buffered 32KB
// chunks; group h consumes k-rows {h, h+16} of each chunk.
// ---------------------------------------------------------------------------
__global__ void __launch_bounds__(NTHR, 1) club_mlp_kernel(
    const float* __restrict__ x1, const float* __restrict__ x2,
    const float* __restrict__ W1, const float* __restrict__ b1,
    const float* __restrict__ W2, const float* __restrict__ b2,
    const float* __restrict__ W3, const float* __restrict__ b3,
    float* __restrict__ out)
{
    extern __shared__ float smem[];
    float* s_part = smem;                      // 16*8*256 = 32768 (128KB)
    float* s_w    = s_part + NG * R * HID;     // 2*KC*HID = 16384 (64KB)
    float* bufA   = s_w + 2 * KC * HID;        // 2048
    float* bufB   = bufA + HID * R;            // 2048
    float* s_x2   = bufB + HID * R;            // 1024
    float* s_m    = s_x2 + R * X2D;            // 128
    float* s_s    = s_m + X2D;                 // 128
    float* s_red  = s_s + X2D;                 // 32

    const int t    = threadIdx.x;
    const int c4   = t & (CT - 1);             // column quad: cols 4*c4..4*c4+3
    const int h    = t >> 6;                   // k-group
    const int row0 = blockIdx.x * R;

    // each thread copies 32 bytes of each 32KB chunk: base offset t*32
    const uint32_t wsm0 = (uint32_t)__cvta_generic_to_shared(s_w);
    const uint32_t wdst = wsm0 + (uint32_t)t * 32u;

    // prefetch chunk 0 of W1 immediately (into buffer 0; global chunk idx 0)
    {
        const float* src = W1 + t * 8;
        cp16(wdst, src);
        cp16(wdst + 16, src + 4);
        cp_commit();
    }

    // stage x1 tile transposed: bufA[c*R + r] = x1[row0+r][c]
    {
        int c = t & 255, rr = t >> 8;
        #pragma unroll
        for (int p = 0; p < 2; p++) {
            int r = rr + p * 4;
            bufA[c * R + r] = x1[(row0 + r) * X1D + c];
        }
    }
    s_x2[t] = x2[row0 * X2D + t];

    if (t < X2D) {
        float ma = 0.f, mb = 0.f;
        #pragma unroll
        for (int b = 0; b < SBLK; b++) {
            ma += g_part_m[b * X2D + t];
            mb += g_part_s[b * X2D + t];
        }
        s_m[t] = ma * (1.0f / N_ROWS);
        s_s[t] = mb * (1.0f / N_ROWS);
    }
    // ordering: the first cp_wait0 + __syncthreads inside run() covers the
    // smem stores above as well.

    auto run = [&](int lidx, const float* __restrict__ Wcur,
                   const float* __restrict__ Wnext,
                   const float* __restrict__ B,
                   const float* __restrict__ inb, float* __restrict__ outb,
                   int act) {
        u64 acc[4][4];
        #pragma unroll
        for (int p = 0; p < 4; p++)
            #pragma unroll
            for (int c = 0; c < 4; c++) acc[p][c] = 0ULL;

        #pragma unroll 1
        for (int c = 0; c < NCHUNK; c++) {
            const int g = lidx * NCHUNK + c;       // global chunk index
            cp_wait0();
            __syncthreads();                       // chunk (g&1) ready for all

            // prefetch next chunk into the other buffer
            const float* srcp = nullptr;
            if (c < NCHUNK - 1)      srcp = Wcur + (c + 1) * (KC * HID);
            else if (Wnext)          srcp = Wnext;
            if (srcp) {
                uint32_t nd = wsm0 +
                    (uint32_t)(((g + 1) & 1) * (KC * HID) * 4) +
                    (uint32_t)t * 32u;
                cp16(nd, srcp + t * 8);
                cp16(nd + 16, srcp + t * 8 + 4);
                cp_commit();
            }

            const float* wb = s_w + (g & 1) * (KC * HID);
            #pragma unroll
            for (int ii = 0; ii < 2; ii++) {
                const int kl = h + ii * 16;        // local k-row in chunk
                float4 w =
                    *reinterpret_cast<const float4*>(wb + kl * HID + 4 * c4);
                u64 wb0 = bcast2(w.x), wb1 = bcast2(w.y);
                u64 wb2 = bcast2(w.z), wb3 = bcast2(w.w);
                const float* ap = inb + (c * KC + kl) * R;
                ulonglong2 q0 = *reinterpret_cast<const ulonglong2*>(ap);
                ulonglong2 q1 = *reinterpret_cast<const ulonglong2*>(ap + 4);
                acc[0][0] = ffma2(q0.x, wb0, acc[0][0]);
                acc[0][1] = ffma2(q0.x, wb1, acc[0][1]);
                acc[0][2] = ffma2(q0.x, wb2, acc[0][2]);
                acc[0][3] = ffma2(q0.x, wb3, acc[0][3]);
                acc[1][0] = ffma2(q0.y, wb0, acc[1][0]);
                acc[1][1] = ffma2(q0.y, wb1, acc[1][1]);
                acc[1][2] = ffma2(q0.y, wb2, acc[1][2]);
                acc[1][3] = ffma2(q0.y, wb3, acc[1][3]);
                acc[2][0] = ffma2(q1.x, wb0, acc[2][0]);
                acc[2][1] = ffma2(q1.x, wb1, acc[2][1]);
                acc[2][2] = ffma2(q1.x, wb2, acc[2][2]);
                acc[2][3] = ffma2(q1.x, wb3, acc[2][3]);
                acc[3][0] = ffma2(q1.y, wb0, acc[3][0]);
                acc[3][1] = ffma2(q1.y, wb1, acc[3][1]);
                acc[3][2] = ffma2(q1.y, wb2, acc[3][2]);
                acc[3][3] = ffma2(q1.y, wb3, acc[3][3]);
            }
        }

        // store partials: u64 slot (h*1024 + p*256 + col) = rows 2p,2p+1
        {
            ulonglong2* pp = reinterpret_cast<ulonglong2*>(s_part) + h * 512;
            #pragma unroll
            for (int p = 0; p < 4; p++) {
                pp[p * 128 + 2 * c4]     = make_ulonglong2(acc[p][0], acc[p][1]);
                pp[p * 128 + 2 * c4 + 1] = make_ulonglong2(acc[p][2], acc[p][3]);
            }
        }
        __syncthreads();

        // packed reduction: thread t owns u64 slot t
        {
            const u64* sp = reinterpret_cast<const u64*>(s_part);
            u64 v = sp[t];
            #pragma unroll
            for (int gg = 1; gg < NG; gg++) v = fadd2(v, sp[gg * 1024 + t]);
            int p   = t >> 8;
            int col = t & 255;
            float lo, hi;
            unpack2(lo, hi, v);
            float bb = B[col];
            lo += bb; hi += bb;
            if (act) { lo = tanhf(lo); hi = tanhf(hi); }
            else     { lo = fmaxf(lo, 0.f); hi = fmaxf(hi, 0.f); }
            reinterpret_cast<float2*>(outb + col * R + 2 * p)[0] =
                make_float2(lo, hi);
        }
        // next run()'s first cp_wait0+syncthreads orders outb for all readers
    };

    run(0, W1, W2,      b1, bufA, bufB, 0);
    run(1, W2, W3,      b2, bufB, bufA, 0);
    run(2, W3, nullptr, b3, bufA, bufB, 1);
    __syncthreads();   // bufB (g, transposed [col][row]) ready for all

    // Epilogue: pos-neg = -0.5*iv*( xi^2 - 2*mu*xi + 2*mu*E[x2] - E[x2^2] )
    float part;
    {
        int d = t & 127;
        int r = t >> 7;
        float mu = bufB[d * R + r];
        float lv = bufB[(X2D + d) * R + r];
        float iv = __expf(-lv);
        float xi = s_x2[r * X2D + d];
        float term = xi * xi - 2.f * mu * xi + 2.f * mu * s_m[d] - s_s[d];
        part = -0.5f * iv * term;
    }
    #pragma unroll
    for (int off = 16; off > 0; off >>= 1)
        part += __shfl_xor_sync(0xffffffffu, part, off);
    if ((t & 31) == 0) s_red[t >> 5] = part;
    __syncthreads();
    if (t < 32) {
        float v = s_red[t];
        #pragma unroll
        for (int off = 16; off > 0; off >>= 1)
            v += __shfl_xor_sync(0xffffffffu, v, off);
        if (t == 0) atomicAdd(out, v * (1.0f / N_ROWS));
    }
}

// ---------------------------------------------------------------------------

extern "C" void kernel_launch(void* const* d_in, const int* in_sizes, int n_in,
                              void* d_out, int out_size)
{
    const float* x1 = (const float*)d_in[0];
    const float* x2 = (const float*)d_in[1];
    const float* W1 = (const float*)d_in[2];
    const float* b1 = (const float*)d_in[3];
    const float* W2 = (const float*)d_in[4];
    const float* b2 = (const float*)d_in[5];
    const float* W3 = (const float*)d_in[6];
    const float* b3 = (const float*)d_in[7];
    float* out = (float*)d_out;

    const int smem_bytes =
        (NG * R * HID + 2 * KC * HID + 2 * HID * R + R * X2D + 2 * X2D + 32) *
        sizeof(float);
    static int attr_set = 0;
    if (!attr_set) {
        cudaFuncSetAttribute(club_mlp_kernel,
                             cudaFuncAttributeMaxDynamicSharedMemorySize,
                             smem_bytes);
        attr_set = 1;
    }

    club_stats_kernel<<<SBLK, 1024>>>(x2, out);
    club_mlp_kernel<<<NBLK, NTHR, smem_bytes>>>(x1, x2, W1, b1, W2, b2, W3, b3, out);
}

// round 7
// speedup vs baseline: 1.5744x; 1.5744x over previous
#include <cuda_runtime.h>
#include <cstdint>

#define N_ROWS 1024
#define X1D 256
#define X2D 128
#define HID 256
#define R 8                 // rows per block
#define NTHR 512
#define NG 8                // k-groups; group h owns k in [h*32, h*32+32)
#define CT 64               // col-threads per group (4 cols each)
#define KPER (HID / NG)     // 32
#define NBLK (N_ROWS / R)   // 128
#define SBLK 8              // stats blocks

typedef unsigned long long u64;

__device__ __forceinline__ u64 bcast2(float w) {
    u64 d; asm("mov.b64 %0, {%1, %1};" : "=l"(d) : "f"(w)); return d;
}
__device__ __forceinline__ u64 ffma2(u64 a, u64 b, u64 c) {
    u64 d; asm("fma.rn.f32x2 %0, %1, %2, %3;" : "=l"(d) : "l"(a), "l"(b), "l"(c));
    return d;
}
__device__ __forceinline__ u64 fadd2(u64 a, u64 b) {
    u64 d; asm("add.rn.f32x2 %0, %1, %2;" : "=l"(d) : "l"(a), "l"(b));
    return d;
}
__device__ __forceinline__ void unpack2(float& lo, float& hi, u64 v) {
    asm("mov.b64 {%0, %1}, %2;" : "=f"(lo), "=f"(hi) : "l"(v));
}

// per-block partial column sums of x2 and x2^2
__device__ float g_part_m[SBLK * X2D];
__device__ float g_part_s[SBLK * X2D];

// ---------------------------------------------------------------------------
// Kernel 1: partial x2 column stats + zero out[0]
// ---------------------------------------------------------------------------
__global__ void __launch_bounds__(1024) club_stats_kernel(
    const float* __restrict__ x2, float* __restrict__ out)
{
    __shared__ float sm[8][128];
    __shared__ float sq[8][128];
    int t = threadIdx.x;
    int c = t & 127;
    int s = t >> 7;
    int r0 = blockIdx.x * 128 + s * 16;
    float a = 0.f, b = 0.f;
    #pragma unroll
    for (int i = 0; i < 16; i++) {
        float v = x2[(r0 + i) * X2D + c];
        a += v;
        b += v * v;
    }
    sm[s][c] = a;
    sq[s][c] = b;
    __syncthreads();
    if (t < 128) {
        float ma = 0.f, mb = 0.f;
        #pragma unroll
        for (int k = 0; k < 8; k++) { ma += sm[k][t]; mb += sq[k][t]; }
        g_part_m[blockIdx.x * X2D + t] = ma;
        g_part_s[blockIdx.x * X2D + t] = mb;
    }
    if (blockIdx.x == 0 && t == 0) out[0] = 0.0f;
}

// ---------------------------------------------------------------------------
// Kernel 2: fused 3-layer MLP + CLUB epilogue, f32x2 packed math.
// 512 threads (128 regs/thread) = 8 k-groups x 64 col-quads. Weights read
// via direct LDG with an explicit depth-2 register pipeline. Activations
// transposed in smem (row-pairs = aligned u64). Per k: 1 LDG.128 + 2 LDS.128
// + 4 bcast + 16 FFMA2.
// ---------------------------------------------------------------------------
__global__ void __launch_bounds__(NTHR, 1) club_mlp_kernel(
    const float* __restrict__ x1, const float* __restrict__ x2,
    const float* __restrict__ W1, const float* __restrict__ b1,
    const float* __restrict__ W2, const float* __restrict__ b2,
    const float* __restrict__ W3, const float* __restrict__ b3,
    float* __restrict__ out)
{
    extern __shared__ float smem[];
    float* s_part = smem;                      // NG*R*HID = 16384 (64KB)
    float* bufA   = s_part + NG * R * HID;     // 2048
    float* bufB   = bufA + HID * R;            // 2048
    float* s_x2   = bufB + HID * R;            // 1024
    float* s_m    = s_x2 + R * X2D;            // 128
    float* s_s    = s_m + X2D;                 // 128
    float* s_red  = s_s + X2D;                 // 16

    const int t    = threadIdx.x;
    const int c4   = t & (CT - 1);             // cols 4*c4..4*c4+3
    const int h    = t >> 6;                   // k-group, 0..7
    const int row0 = blockIdx.x * R;

    // stage x1 tile transposed: bufA[c*R + r] = x1[row0+r][c]
    {
        int c = t & 255, rr = t >> 8;          // rr in {0,1}
        #pragma unroll
        for (int p = 0; p < 4; p++) {
            int r = rr + p * 2;
            bufA[c * R + r] = x1[(row0 + r) * X1D + c];
        }
    }
    // x2 tile: 1024 floats, 2 per thread
    s_x2[t]        = x2[row0 * X2D + t];
    s_x2[t + NTHR] = x2[row0 * X2D + t + NTHR];

    if (t < X2D) {
        float ma = 0.f, mb = 0.f;
        #pragma unroll
        for (int b = 0; b < SBLK; b++) {
            ma += g_part_m[b * X2D + t];
            mb += g_part_s[b * X2D + t];
        }
        s_m[t] = ma * (1.0f / N_ROWS);
        s_s[t] = mb * (1.0f / N_ROWS);
    }
    __syncthreads();

    auto run = [&](const float* __restrict__ W, const float* __restrict__ B,
                   const float* __restrict__ inb, float* __restrict__ outb,
                   int act) {
        u64 acc[4][4];
        #pragma unroll
        for (int p = 0; p < 4; p++)
            #pragma unroll
            for (int c = 0; c < 4; c++) acc[p][c] = 0ULL;

        // weights: W[k][4*c4 .. 4*c4+3], k = h*KPER + kk
        const float4* wp =
            reinterpret_cast<const float4*>(W + (h * KPER) * HID) + c4;
        const ulonglong2* ipu =
            reinterpret_cast<const ulonglong2*>(inb + (h * KPER) * R);

        // depth-2 register pipeline on the weight loads
        float4 wreg[2];
        wreg[0] = __ldg(wp);
        wreg[1] = __ldg(wp + (HID / 4));

        #pragma unroll
        for (int kk = 0; kk < KPER; kk++) {
            float4 w = wreg[kk & 1];
            if (kk + 2 < KPER)
                wreg[kk & 1] = __ldg(wp + (kk + 2) * (HID / 4));
            u64 wb0 = bcast2(w.x), wb1 = bcast2(w.y);
            u64 wb2 = bcast2(w.z), wb3 = bcast2(w.w);
            ulonglong2 q0 = ipu[2 * kk];       // rows (0,1),(2,3)
            ulonglong2 q1 = ipu[2 * kk + 1];   // rows (4,5),(6,7)
            acc[0][0] = ffma2(q0.x, wb0, acc[0][0]);
            acc[0][1] = ffma2(q0.x, wb1, acc[0][1]);
            acc[0][2] = ffma2(q0.x, wb2, acc[0][2]);
            acc[0][3] = ffma2(q0.x, wb3, acc[0][3]);
            acc[1][0] = ffma2(q0.y, wb0, acc[1][0]);
            acc[1][1] = ffma2(q0.y, wb1, acc[1][1]);
            acc[1][2] = ffma2(q0.y, wb2, acc[1][2]);
            acc[1][3] = ffma2(q0.y, wb3, acc[1][3]);
            acc[2][0] = ffma2(q1.x, wb0, acc[2][0]);
            acc[2][1] = ffma2(q1.x, wb1, acc[2][1]);
            acc[2][2] = ffma2(q1.x, wb2, acc[2][2]);
            acc[2][3] = ffma2(q1.x, wb3, acc[2][3]);
            acc[3][0] = ffma2(q1.y, wb0, acc[3][0]);
            acc[3][1] = ffma2(q1.y, wb1, acc[3][1]);
            acc[3][2] = ffma2(q1.y, wb2, acc[3][2]);
            acc[3][3] = ffma2(q1.y, wb3, acc[3][3]);
        }

        // store partials: group h, u64 slot p*256 + col (rows 2p,2p+1)
        {
            ulonglong2* pp = reinterpret_cast<ulonglong2*>(s_part) + h * 512;
            #pragma unroll
            for (int p = 0; p < 4; p++) {
                pp[p * 128 + 2 * c4]     = make_ulonglong2(acc[p][0], acc[p][1]);
                pp[p * 128 + 2 * c4 + 1] = make_ulonglong2(acc[p][2], acc[p][3]);
            }
        }
        __syncthreads();

        // packed reduction: 1024 u64 slots, 2 per thread
        {
            const u64* sp = reinterpret_cast<const u64*>(s_part);
            #pragma unroll
            for (int s = 0; s < 2; s++) {
                int slot = t + s * NTHR;
                u64 v = sp[slot];
                #pragma unroll
                for (int gg = 1; gg < NG; gg++)
                    v = fadd2(v, sp[gg * 1024 + slot]);
                int p   = slot >> 8;
                int col = slot & 255;
                float lo, hi;
                unpack2(lo, hi, v);
                float bb = B[col];
                lo += bb; hi += bb;
                if (act) { lo = tanhf(lo); hi = tanhf(hi); }
                else     { lo = fmaxf(lo, 0.f); hi = fmaxf(hi, 0.f); }
                reinterpret_cast<float2*>(outb + col * R + 2 * p)[0] =
                    make_float2(lo, hi);
            }
        }
        __syncthreads();
    };

    run(W1, b1, bufA, bufB, 0);
    run(W2, b2, bufB, bufA, 0);
    run(W3, b3, bufA, bufB, 1);   // g (tanh) in bufB, transposed [col][r]

    // Epilogue: pos-neg = -0.5*iv*( xi^2 - 2*mu*xi + 2*mu*E[x2] - E[x2^2] )
    float part = 0.f;
    #pragma unroll
    for (int s = 0; s < 2; s++) {
        int idx = t + s * NTHR;   // idx = r*128 + d
        int d = idx & 127;
        int r = idx >> 7;
        float mu = bufB[d * R + r];
        float lv = bufB[(X2D + d) * R + r];
        float iv = __expf(-lv);
        float xi = s_x2[r * X2D + d];
        float term = xi * xi - 2.f * mu * xi + 2.f * mu * s_m[d] - s_s[d];
        part += -0.5f * iv * term;
    }
    #pragma unroll
    for (int off = 16; off > 0; off >>= 1)
        part += __shfl_xor_sync(0xffffffffu, part, off);
    if ((t & 31) == 0) s_red[t >> 5] = part;
    __syncthreads();
    if (t < 16) {
        float v = s_red[t];
        #pragma unroll
        for (int off = 8; off > 0; off >>= 1)
            v += __shfl_xor_sync(0xffffu, v, off);
        if (t == 0) atomicAdd(out, v * (1.0f / N_ROWS));
    }
}

// ---------------------------------------------------------------------------

extern "C" void kernel_launch(void* const* d_in, const int* in_sizes, int n_in,
                              void* d_out, int out_size)
{
    const float* x1 = (const float*)d_in[0];
    const float* x2 = (const float*)d_in[1];
    const float* W1 = (const float*)d_in[2];
    const float* b1 = (const float*)d_in[3];
    const float* W2 = (const float*)d_in[4];
    const float* b2 = (const float*)d_in[5];
    const float* W3 = (const float*)d_in[6];
    const float* b3 = (const float*)d_in[7];
    float* out = (float*)d_out;

    const int smem_bytes =
        (NG * R * HID + 2 * HID * R + R * X2D + 2 * X2D + 16) * sizeof(float);
    static int attr_set = 0;
    if (!attr_set) {
        cudaFuncSetAttribute(club_mlp_kernel,
                             cudaFuncAttributeMaxDynamicSharedMemorySize,
                             smem_bytes);
        attr_set = 1;
    }

    club_stats_kernel<<<SBLK, 1024>>>(x2, out);
    club_mlp_kernel<<<NBLK, NTHR, smem_bytes>>>(x1, x2, W1, b1, W2, b2, W3, b3, out);
}